// round 4
// baseline (speedup 1.0000x reference)
#include <cuda_runtime.h>
#include <math.h>

#define BATCHN 1024
#define NFEAT 256
#define NSAMP 100000
#define INV_TEMP 20.0f
#define BM 64
#define BN 64
#define BK 32
#define SCHUNKS 30
#define NTILES ((NSAMP + BN - 1) / BN)   // 1563
#define AS_STRIDE 66                      // BM + 2: even (8B-aligned float2/ull loads)
#define BS_STRIDE 68                      // BN + 4: multiple of 4 (16B-aligned float4 loads)

// Scratch (no allocations allowed anywhere)
__device__ float g_partM[SCHUNKS * BATCHN];
__device__ float g_partS[SCHUNKS * BATCHN];
__device__ float g_nll[BATCHN];

__device__ __forceinline__ unsigned long long pack2(float lo, float hi) {
    unsigned long long r;
    asm("mov.b64 %0, {%1, %2};" : "=l"(r) : "f"(lo), "f"(hi));
    return r;
}
// Packed f32x2 FMA (sm_103a FFMA2) — 2 fp32 FMAs per fma-pipe slot
__device__ __forceinline__ void fma2(unsigned long long& d, unsigned long long a, unsigned long long b) {
    asm("fma.rn.f32x2 %0, %1, %2, %0;" : "+l"(d) : "l"(a), "l"(b));
}

union F2U { unsigned long long u; float2 f; };

// ---------------------------------------------------------------------------
// Kernel 1: per (row-tile, sample-chunk) block: GEMM + online softmax partials
// ---------------------------------------------------------------------------
__global__ __launch_bounds__(256)
void partial_lse_kernel(const float* __restrict__ A, const float* __restrict__ F) {
    __shared__ __align__(16) float As[BK * AS_STRIDE];   // [k][m]
    __shared__ __align__(16) float Bs[BK * BS_STRIDE];   // [k][n]
    __shared__ float red[BM * 17];
    __shared__ float rowM[BM], rowS[BM], newM[BM];

    const int tid = threadIdx.x;
    const int tx = tid & 15, ty = tid >> 4;        // 16x16 thread grid
    const int m0 = blockIdx.y * BM;
    const int chunk = blockIdx.x;

    if (tid < BM) { rowM[tid] = -INFINITY; rowS[tid] = 0.f; }

    const int lr = tid >> 3;                       // 0..31 (tile row for loads)
    const int lk = (tid & 7) * 4;                  // k offset within BK

    const int t0 = (chunk * NTILES) / SCHUNKS;
    const int t1 = ((chunk + 1) * NTILES) / SCHUNKS;

    for (int t = t0; t < t1; ++t) {
        const int n0 = t * BN;
        const int nvalid = NSAMP - n0;             // >= BN except last tile

        unsigned long long acc[2][4];              // row-pairs x 4 cols, packed f32x2
        #pragma unroll
        for (int p = 0; p < 2; ++p)
            #pragma unroll
            for (int j = 0; j < 4; ++j) acc[p][j] = 0ull;

        for (int kt = 0; kt < NFEAT; kt += BK) {
            __syncthreads();
            // A tile 64x32 -> As[k][m] (transpose), coalesced float4 global reads
            {
                float4 a0 = *(const float4*)&A[(size_t)(m0 + lr) * NFEAT + kt + lk];
                float4 a1 = *(const float4*)&A[(size_t)(m0 + lr + 32) * NFEAT + kt + lk];
                As[(lk + 0) * AS_STRIDE + lr] = a0.x;
                As[(lk + 1) * AS_STRIDE + lr] = a0.y;
                As[(lk + 2) * AS_STRIDE + lr] = a0.z;
                As[(lk + 3) * AS_STRIDE + lr] = a0.w;
                As[(lk + 0) * AS_STRIDE + lr + 32] = a1.x;
                As[(lk + 1) * AS_STRIDE + lr + 32] = a1.y;
                As[(lk + 2) * AS_STRIDE + lr + 32] = a1.z;
                As[(lk + 3) * AS_STRIDE + lr + 32] = a1.w;
            }
            // B tile 64x32 -> Bs[k][n], guard tail rows
            {
                const int r0 = n0 + lr, r1 = n0 + lr + 32;
                float4 b0 = (r0 < NSAMP) ? *(const float4*)&F[(size_t)r0 * NFEAT + kt + lk]
                                         : make_float4(0.f, 0.f, 0.f, 0.f);
                float4 b1 = (r1 < NSAMP) ? *(const float4*)&F[(size_t)r1 * NFEAT + kt + lk]
                                         : make_float4(0.f, 0.f, 0.f, 0.f);
                Bs[(lk + 0) * BS_STRIDE + lr] = b0.x;
                Bs[(lk + 1) * BS_STRIDE + lr] = b0.y;
                Bs[(lk + 2) * BS_STRIDE + lr] = b0.z;
                Bs[(lk + 3) * BS_STRIDE + lr] = b0.w;
                Bs[(lk + 0) * BS_STRIDE + lr + 32] = b1.x;
                Bs[(lk + 1) * BS_STRIDE + lr + 32] = b1.y;
                Bs[(lk + 2) * BS_STRIDE + lr + 32] = b1.z;
                Bs[(lk + 3) * BS_STRIDE + lr + 32] = b1.w;
            }
            __syncthreads();
            #pragma unroll 8
            for (int k = 0; k < BK; ++k) {
                unsigned long long a01 = *(const unsigned long long*)&As[k * AS_STRIDE + ty * 4];
                unsigned long long a23 = *(const unsigned long long*)&As[k * AS_STRIDE + ty * 4 + 2];
                float4 b = *(const float4*)&Bs[k * BS_STRIDE + tx * 4];
                unsigned long long bb0 = pack2(b.x, b.x);
                unsigned long long bb1 = pack2(b.y, b.y);
                unsigned long long bb2 = pack2(b.z, b.z);
                unsigned long long bb3 = pack2(b.w, b.w);
                fma2(acc[0][0], a01, bb0); fma2(acc[0][1], a01, bb1);
                fma2(acc[0][2], a01, bb2); fma2(acc[0][3], a01, bb3);
                fma2(acc[1][0], a23, bb0); fma2(acc[1][1], a23, bb1);
                fma2(acc[1][2], a23, bb2); fma2(acc[1][3], a23, bb3);
            }
        }

        // Unpack logits = acc * (1/temp)
        float l[4][4];
        #pragma unroll
        for (int p = 0; p < 2; ++p)
            #pragma unroll
            for (int j = 0; j < 4; ++j) {
                F2U cv; cv.u = acc[p][j];
                l[2 * p + 0][j] = cv.f.x * INV_TEMP;
                l[2 * p + 1][j] = cv.f.y * INV_TEMP;
            }

        // Tile row-max (16 threads per row hold 4 cols each)
        #pragma unroll
        for (int i = 0; i < 4; ++i) {
            float mx = -INFINITY;
            #pragma unroll
            for (int j = 0; j < 4; ++j)
                if (tx * 4 + j < nvalid) mx = fmaxf(mx, l[i][j]);
            red[(ty * 4 + i) * 17 + tx] = mx;
        }
        __syncthreads();
        if (tx == 0) {
            #pragma unroll
            for (int i = 0; i < 4; ++i) {
                const int r = ty * 4 + i;
                float mx = red[r * 17];
                #pragma unroll
                for (int u = 1; u < 16; ++u) mx = fmaxf(mx, red[r * 17 + u]);
                newM[r] = fmaxf(mx, rowM[r]);
            }
        }
        __syncthreads();
        // Partial exp-sums against newM
        #pragma unroll
        for (int i = 0; i < 4; ++i) {
            const int r = ty * 4 + i;
            const float m = newM[r];
            float s = 0.f;
            #pragma unroll
            for (int j = 0; j < 4; ++j)
                if (tx * 4 + j < nvalid) s += __expf(l[i][j] - m);
            red[r * 17 + tx] = s;
        }
        __syncthreads();
        if (tx == 0) {
            #pragma unroll
            for (int i = 0; i < 4; ++i) {
                const int r = ty * 4 + i;
                float s = 0.f;
                #pragma unroll
                for (int u = 0; u < 16; ++u) s += red[r * 17 + u];
                rowS[r] = rowS[r] * __expf(rowM[r] - newM[r]) + s;
                rowM[r] = newM[r];
            }
        }
        __syncthreads();
    }

    if (tid < BM) {
        g_partM[chunk * BATCHN + m0 + tid] = rowM[tid];
        g_partS[chunk * BATCHN + m0 + tid] = rowS[tid];
    }
}

// ---------------------------------------------------------------------------
// Kernel 2: warp-per-row merge of chunk partials + target logit -> NLL
// Targets are int32 (JAX default x64-disabled downcasts jnp.int64 -> int32).
// ---------------------------------------------------------------------------
__global__ __launch_bounds__(256)
void merge_nll_kernel(const float* __restrict__ A, const float* __restrict__ F,
                      const int* __restrict__ T) {
    const int gw = (blockIdx.x * blockDim.x + threadIdx.x) >> 5;  // row
    const int lane = threadIdx.x & 31;
    if (gw >= BATCHN) return;

    float M = -INFINITY, S = 0.f;
    if (lane < SCHUNKS) {
        M = g_partM[lane * BATCHN + gw];
        S = g_partS[lane * BATCHN + gw];
    }
    #pragma unroll
    for (int off = 16; off > 0; off >>= 1) {
        float oM = __shfl_down_sync(0xffffffffu, M, off);
        float oS = __shfl_down_sync(0xffffffffu, S, off);
        float nm = fmaxf(M, oM);
        if (nm == -INFINITY) { S = 0.f; }
        else { S = S * __expf(M - nm) + oS * __expf(oM - nm); }
        M = nm;
    }

    int tg = T[gw];
    tg = (tg < 0) ? 0 : ((tg >= NSAMP) ? NSAMP - 1 : tg);   // defensive clamp
    const float* ar = A + (size_t)gw * NFEAT;
    const float* fr = F + (size_t)tg * NFEAT;
    float td = 0.f;
    #pragma unroll
    for (int k = lane; k < NFEAT; k += 32) td += ar[k] * fr[k];
    #pragma unroll
    for (int off = 16; off > 0; off >>= 1) td += __shfl_down_sync(0xffffffffu, td, off);

    if (lane == 0) g_nll[gw] = M + logf(S) - td * INV_TEMP;
}

// ---------------------------------------------------------------------------
// Kernel 3: mean over batch
// ---------------------------------------------------------------------------
__global__ __launch_bounds__(256)
void mean_kernel(float* __restrict__ out) {
    __shared__ float sm[256];
    const int tid = threadIdx.x;
    float v = 0.f;
    for (int i = tid; i < BATCHN; i += 256) v += g_nll[i];
    sm[tid] = v;
    __syncthreads();
    for (int s = 128; s > 0; s >>= 1) {
        if (tid < s) sm[tid] += sm[tid + s];
        __syncthreads();
    }
    if (tid == 0) out[0] = sm[0] / (float)BATCHN;
}

extern "C" void kernel_launch(void* const* d_in, const int* in_sizes, int n_in,
                              void* d_out, int out_size) {
    const float* A = nullptr;   // inputs   [1024, 256]  f32
    const float* F = nullptr;   // features [100000,256] f32
    const int*   T = nullptr;   // targets  [1024]       i32
    for (int i = 0; i < n_in; ++i) {
        if (in_sizes[i] == BATCHN * NFEAT)      A = (const float*)d_in[i];
        else if (in_sizes[i] == NSAMP * NFEAT)  F = (const float*)d_in[i];
        else if (in_sizes[i] == BATCHN)         T = (const int*)d_in[i];
    }
    dim3 grid(SCHUNKS, BATCHN / BM);
    partial_lse_kernel<<<grid, 256>>>(A, F);
    merge_nll_kernel<<<BATCHN / 8, 256>>>(A, F, T);
    mean_kernel<<<1, 256>>>((float*)d_out);
    (void)out_size;
}

// round 7
// speedup vs baseline: 4.1695x; 4.1695x over previous
#include <cuda_runtime.h>
#include <cuda_bf16.h>
#include <math.h>
#include <stdint.h>

#define BATCHN 1024
#define NFEAT 256
#define NSAMP 100000
#define INV_TEMP 20.0f
#define KL2E 28.85390081777927f      /* 20 * log2(e) */

#define MTILE 128
#define NTILE 64
#define NCHUNK 18
#define NTN ((NSAMP + NTILE - 1) / NTILE)   /* 1563 */

#define BSTRIDE 528                   /* 512B row + 16B pad: conflict-free ldmatrix */
#define BBYTES (NTILE * BSTRIDE)      /* 33792 per dtype */
#define BUFBYTES (2 * BBYTES)         /* hi + lo = 67584 */
#define SM_TOTAL (2 * BUFBYTES)       /* double buffered = 135168 */

/* ------------------------- device scratch (no allocs) --------------------- */
__device__ __nv_bfloat16 g_Fhi[(size_t)NSAMP * NFEAT];
__device__ __nv_bfloat16 g_Flo[(size_t)NSAMP * NFEAT];
__device__ float g_partM[NCHUNK * BATCHN];
__device__ float g_partS[NCHUNK * BATCHN];
__device__ float g_nll[BATCHN];

/* ------------------------------ helpers ---------------------------------- */
__device__ __forceinline__ uint32_t smem_u32(const void* p) {
    uint32_t a;
    asm("{ .reg .u64 t; cvta.to.shared.u64 t, %1; cvt.u32.u64 %0, t; }"
        : "=r"(a) : "l"(p));
    return a;
}
__device__ __forceinline__ void cp16(uint32_t dst, const void* gsrc) {
    asm volatile("cp.async.cg.shared.global [%0], [%1], 16;"
                 :: "r"(dst), "l"(__cvta_generic_to_global(gsrc)) : "memory");
}
__device__ __forceinline__ void sts128z(uint32_t dst) {
    asm volatile("st.shared.v4.b32 [%0], {%1, %1, %1, %1};" :: "r"(dst), "r"(0u) : "memory");
}
#define CP_COMMIT() asm volatile("cp.async.commit_group;" ::: "memory")
#define CP_WAIT0()  asm volatile("cp.async.wait_group 0;" ::: "memory")

__device__ __forceinline__ void ldsm4(uint32_t* r, uint32_t addr) {
    asm volatile("ldmatrix.sync.aligned.m8n8.x4.shared.b16 {%0,%1,%2,%3}, [%4];"
                 : "=r"(r[0]), "=r"(r[1]), "=r"(r[2]), "=r"(r[3]) : "r"(addr));
}
__device__ __forceinline__ void mma16816(float* d, const uint32_t* a,
                                         uint32_t b0, uint32_t b1) {
    asm volatile("mma.sync.aligned.m16n8k16.row.col.f32.bf16.bf16.f32 "
                 "{%0,%1,%2,%3}, {%4,%5,%6,%7}, {%8,%9}, {%0,%1,%2,%3};"
                 : "+f"(d[0]), "+f"(d[1]), "+f"(d[2]), "+f"(d[3])
                 : "r"(a[0]), "r"(a[1]), "r"(a[2]), "r"(a[3]), "r"(b0), "r"(b1));
}

/* software exp2: deg-5 poly; input clamped at -126 (underflow -> ~0) */
__device__ __forceinline__ float fexp2(float y) {
    y = fmaxf(y, -126.0f);
    float n = rintf(y);
    float t = y - n;
    float p = 0.00133336f;
    p = fmaf(p, t, 0.00961801f);
    p = fmaf(p, t, 0.05550411f);
    p = fmaf(p, t, 0.24022651f);
    p = fmaf(p, t, 0.69314718f);
    p = fmaf(p, t, 1.0f);
    float sc = __int_as_float((int)fmaf(n, 8388608.0f, 1065353216.0f));
    return p * sc;
}

/* -------------------- kernel 0: F -> bf16 hi/lo split --------------------- */
__global__ __launch_bounds__(256)
void convF_kernel(const float* __restrict__ F) {
    size_t i = ((size_t)blockIdx.x * 256 + threadIdx.x) * 8;
    float4 x0 = *(const float4*)(F + i);
    float4 x1 = *(const float4*)(F + i + 4);
    float xs[8] = {x0.x, x0.y, x0.z, x0.w, x1.x, x1.y, x1.z, x1.w};
    __nv_bfloat16 hi[8], lo[8];
#pragma unroll
    for (int j = 0; j < 8; ++j) {
        hi[j] = __float2bfloat16(xs[j]);
        lo[j] = __float2bfloat16(xs[j] - __bfloat162float(hi[j]));
    }
    *(uint4*)((char*)g_Fhi + i * 2) = *(uint4*)hi;
    *(uint4*)((char*)g_Flo + i * 2) = *(uint4*)lo;
}

/* ----------------- B tile prefetch: gmem -> smem (n-major) ---------------- */
__device__ __forceinline__ void prefetch_tile(uint32_t dstbase, int n0, int tid) {
#pragma unroll
    for (int i = 0; i < 16; ++i) {
        int seg = tid + (i << 8);            /* 0..4095 */
        int dt  = seg >> 11;                 /* 0 = hi, 1 = lo */
        int s2  = seg & 2047;
        int row = s2 >> 5;                   /* 0..63 sample row */
        int ch  = s2 & 31;                   /* 16B chunk within 512B row */
        uint32_t dst = dstbase + (uint32_t)dt * BBYTES + (uint32_t)row * BSTRIDE + (ch << 4);
        int gr = n0 + row;
        if (gr < NSAMP) {
            const __nv_bfloat16* g = dt ? g_Flo : g_Fhi;
            cp16(dst, (const char*)g + (((size_t)gr) << 9) + (ch << 4));
        } else {
            sts128z(dst);
        }
    }
    CP_COMMIT();
}

/* --------------- kernel 1: mma.sync fused GEMM + online LSE --------------- */
__global__ void __launch_bounds__(256, 1)
fused_lse_mma(const float* __restrict__ A) {
    extern __shared__ __align__(16) char smem[];
    const uint32_t sb = smem_u32(smem);
    const int tid = threadIdx.x;
    const int lane = tid & 31;
    const int wid = tid >> 5;
    const int chunk = blockIdx.x;
    const int m0 = blockIdx.y * MTILE;

    /* ---- A fragments (hi/lo) resident in registers: m16 x k256 per warp --- */
    uint32_t Ah[16][4], Al[16][4];
    {
        const int r0 = m0 + wid * 16 + (lane >> 2);
        const float* A0 = A + (size_t)r0 * NFEAT;
        const float* A1 = A0 + 8 * NFEAT;
        const int kq = (lane & 3) * 2;
#pragma unroll
        for (int kc = 0; kc < 16; ++kc) {
#pragma unroll
            for (int q = 0; q < 4; ++q) {
                const float* src = ((q & 1) ? A1 : A0) + kc * 16 + ((q >> 1) << 3) + kq;
                float2 v = *(const float2*)src;
                __nv_bfloat16 h0 = __float2bfloat16(v.x);
                __nv_bfloat16 h1 = __float2bfloat16(v.y);
                __nv_bfloat16 l0 = __float2bfloat16(v.x - __bfloat162float(h0));
                __nv_bfloat16 l1 = __float2bfloat16(v.y - __bfloat162float(h1));
                Ah[kc][q] = ((uint32_t)__bfloat16_as_ushort(h1) << 16) | __bfloat16_as_ushort(h0);
                Al[kc][q] = ((uint32_t)__bfloat16_as_ushort(l1) << 16) | __bfloat16_as_ushort(l0);
            }
        }
    }

    const int t0 = (chunk * NTN) / NCHUNK;
    const int t1 = ((chunk + 1) * NTN) / NCHUNK;

    float mr0 = -INFINITY, sr0 = 0.f;   /* rows lane/4 and lane/4+8 of warp block */
    float mr1 = -INFINITY, sr1 = 0.f;

    /* ldmatrix lane addressing (constant per thread) */
    const uint32_t mat = lane >> 3;
    const uint32_t nrow = (lane & 7) + ((mat >> 1) << 3);
    const uint32_t kadd = (mat & 1) << 4;
    const int cbase = (lane & 3) * 2;

    prefetch_tile(sb, t0 * NTILE, tid);

    for (int t = t0; t < t1; ++t) {
        const uint32_t buf = sb + (uint32_t)((t - t0) & 1) * BUFBYTES;
        CP_WAIT0();
        __syncthreads();
        if (t + 1 < t1)
            prefetch_tile(sb + (uint32_t)((t - t0 + 1) & 1) * BUFBYTES,
                          (t + 1) * NTILE, tid);

        float acc[8][4];
#pragma unroll
        for (int nf = 0; nf < 8; ++nf)
#pragma unroll
            for (int c = 0; c < 4; ++c) acc[nf][c] = 0.f;

#pragma unroll
        for (int kc = 0; kc < 16; ++kc) {
#pragma unroll
            for (int nfp = 0; nfp < 4; ++nfp) {
                uint32_t ah = buf + (nfp * 16 + nrow) * BSTRIDE + kc * 32 + kadd;
                uint32_t bh[4], bl[4];
                ldsm4(bh, ah);
                ldsm4(bl, ah + BBYTES);
                mma16816(acc[nfp * 2], Ah[kc], bh[0], bh[1]);
                mma16816(acc[nfp * 2], Ah[kc], bl[0], bl[1]);
                mma16816(acc[nfp * 2], Al[kc], bh[0], bh[1]);
                mma16816(acc[nfp * 2 + 1], Ah[kc], bh[2], bh[3]);
                mma16816(acc[nfp * 2 + 1], Ah[kc], bl[2], bl[3]);
                mma16816(acc[nfp * 2 + 1], Al[kc], bh[2], bh[3]);
            }
        }

        /* -------- epilogue: per-row online (m, s); quad-shfls only -------- */
        const int n0 = t * NTILE;
        int nv = NSAMP - n0; if (nv > NTILE) nv = NTILE;

        float mx0 = -INFINITY, mx1 = -INFINITY;
#pragma unroll
        for (int nf = 0; nf < 8; ++nf) {
            const int c0 = nf * 8 + cbase;
            const float x0 = (c0 < nv)     ? acc[nf][0] : -INFINITY;
            const float x1 = (c0 + 1 < nv) ? acc[nf][1] : -INFINITY;
            const float x2 = (c0 < nv)     ? acc[nf][2] : -INFINITY;
            const float x3 = (c0 + 1 < nv) ? acc[nf][3] : -INFINITY;
            mx0 = fmaxf(mx0, fmaxf(x0, x1));
            mx1 = fmaxf(mx1, fmaxf(x2, x3));
        }
        mx0 = fmaxf(mx0, __shfl_xor_sync(0xffffffffu, mx0, 1));
        mx0 = fmaxf(mx0, __shfl_xor_sync(0xffffffffu, mx0, 2));
        mx1 = fmaxf(mx1, __shfl_xor_sync(0xffffffffu, mx1, 1));
        mx1 = fmaxf(mx1, __shfl_xor_sync(0xffffffffu, mx1, 2));

        const float nm0 = fmaxf(mr0, mx0);
        const float nm1 = fmaxf(mr1, mx1);
        float e0 = 0.f, e1 = 0.f;
#pragma unroll
        for (int nf = 0; nf < 8; ++nf) {
            const int c0 = nf * 8 + cbase;
            const float x0 = (c0 < nv)     ? acc[nf][0] : -INFINITY;
            const float x1 = (c0 + 1 < nv) ? acc[nf][1] : -INFINITY;
            const float x2 = (c0 < nv)     ? acc[nf][2] : -INFINITY;
            const float x3 = (c0 + 1 < nv) ? acc[nf][3] : -INFINITY;
            e0 += fexp2((x0 - nm0) * KL2E) + fexp2((x1 - nm0) * KL2E);
            e1 += fexp2((x2 - nm1) * KL2E) + fexp2((x3 - nm1) * KL2E);
        }
        e0 += __shfl_xor_sync(0xffffffffu, e0, 1);
        e0 += __shfl_xor_sync(0xffffffffu, e0, 2);
        e1 += __shfl_xor_sync(0xffffffffu, e1, 1);
        e1 += __shfl_xor_sync(0xffffffffu, e1, 2);

        sr0 = sr0 * fexp2((mr0 - nm0) * KL2E) + e0;  mr0 = nm0;
        sr1 = sr1 * fexp2((mr1 - nm1) * KL2E) + e1;  mr1 = nm1;
    }

    if ((lane & 3) == 0) {
        const int rbase = m0 + wid * 16 + (lane >> 2);
        g_partM[chunk * BATCHN + rbase]     = mr0 * INV_TEMP;
        g_partS[chunk * BATCHN + rbase]     = sr0;
        g_partM[chunk * BATCHN + rbase + 8] = mr1 * INV_TEMP;
        g_partS[chunk * BATCHN + rbase + 8] = sr1;
    }
}

/* ------------- kernel 2: merge chunk partials + target dot -> NLL --------- */
__global__ __launch_bounds__(256)
void merge_nll_kernel(const float* __restrict__ A, const float* __restrict__ F,
                      const int* __restrict__ T) {
    const int gw = (blockIdx.x * blockDim.x + threadIdx.x) >> 5;
    const int lane = threadIdx.x & 31;
    if (gw >= BATCHN) return;

    float M = -INFINITY, S = 0.f;
    if (lane < NCHUNK) {
        M = g_partM[lane * BATCHN + gw];
        S = g_partS[lane * BATCHN + gw];
    }
#pragma unroll
    for (int off = 16; off > 0; off >>= 1) {
        float oM = __shfl_down_sync(0xffffffffu, M, off);
        float oS = __shfl_down_sync(0xffffffffu, S, off);
        float nm = fmaxf(M, oM);
        if (nm == -INFINITY) { S = 0.f; }
        else { S = S * __expf(M - nm) + oS * __expf(oM - nm); }
        M = nm;
    }

    int tg = T[gw];
    tg = (tg < 0) ? 0 : ((tg >= NSAMP) ? NSAMP - 1 : tg);
    const float* ar = A + (size_t)gw * NFEAT;
    const float* fr = F + (size_t)tg * NFEAT;
    float td = 0.f;
#pragma unroll
    for (int k = lane; k < NFEAT; k += 32) td += ar[k] * fr[k];
#pragma unroll
    for (int off = 16; off > 0; off >>= 1) td += __shfl_down_sync(0xffffffffu, td, off);

    if (lane == 0) g_nll[gw] = M + logf(S) - td * INV_TEMP;
}

/* ---------------------------- kernel 3: mean ------------------------------ */
__global__ __launch_bounds__(256)
void mean_kernel(float* __restrict__ out) {
    __shared__ float sm[256];
    const int tid = threadIdx.x;
    float v = 0.f;
    for (int i = tid; i < BATCHN; i += 256) v += g_nll[i];
    sm[tid] = v;
    __syncthreads();
    for (int s = 128; s > 0; s >>= 1) {
        if (tid < s) sm[tid] += sm[tid + s];
        __syncthreads();
    }
    if (tid == 0) out[0] = sm[0] / (float)BATCHN;
}

extern "C" void kernel_launch(void* const* d_in, const int* in_sizes, int n_in,
                              void* d_out, int out_size) {
    const float* A = nullptr;   /* inputs   [1024, 256]  f32 */
    const float* F = nullptr;   /* features [100000,256] f32 */
    const int*   T = nullptr;   /* targets  [1024]       i32 */
    for (int i = 0; i < n_in; ++i) {
        if (in_sizes[i] == BATCHN * NFEAT)      A = (const float*)d_in[i];
        else if (in_sizes[i] == NSAMP * NFEAT)  F = (const float*)d_in[i];
        else if (in_sizes[i] == BATCHN)         T = (const int*)d_in[i];
    }
    cudaFuncSetAttribute(fused_lse_mma,
                         cudaFuncAttributeMaxDynamicSharedMemorySize, SM_TOTAL);
    convF_kernel<<<(NSAMP * NFEAT) / (256 * 8), 256>>>(F);
    fused_lse_mma<<<dim3(NCHUNK, BATCHN / MTILE), 256, SM_TOTAL>>>(A);
    merge_nll_kernel<<<BATCHN / 8, 256>>>(A, F, T);
    mean_kernel<<<1, 256>>>((float*)d_out);
    (void)out_size;
}

// round 9
// speedup vs baseline: 5.9310x; 1.4225x over previous
#include <cuda_runtime.h>
#include <cuda_bf16.h>
#include <math.h>
#include <stdint.h>

#define BATCHN 1024
#define NFEAT 256
#define NSAMP 100000
#define INV_TEMP 20.0f
#define KL2E 28.85390081777927f      /* 20 * log2(e) */
#define SKIP_TH 1.05f                /* dot-units; 1.05*KL2E > 30 -> 2^-30 */

#define MTILE 128
#define NTILE 64
#define NCHUNK 18
#define NTN ((NSAMP + NTILE - 1) / NTILE)   /* 1563 */

#define BSTRIDE 528                   /* 512B row + 16B pad: conflict-free ldmatrix */
#define BBYTES (NTILE * BSTRIDE)      /* 33792 */
#define SM_TOTAL (2 * BBYTES)         /* double buffered hi-only = 67584 */

/* ------------------------- device scratch (no allocs) --------------------- */
__device__ __nv_bfloat16 g_Fhi[(size_t)NSAMP * NFEAT];
__device__ float g_partM[NCHUNK * BATCHN];
__device__ float g_partS[NCHUNK * BATCHN];
__device__ float g_nll[BATCHN];

/* ------------------------------ helpers ---------------------------------- */
__device__ __forceinline__ uint32_t smem_u32(const void* p) {
    uint32_t a;
    asm("{ .reg .u64 t; cvta.to.shared.u64 t, %1; cvt.u32.u64 %0, t; }"
        : "=r"(a) : "l"(p));
    return a;
}
__device__ __forceinline__ void cp16(uint32_t dst, const void* gsrc) {
    asm volatile("cp.async.cg.shared.global [%0], [%1], 16;"
                 :: "r"(dst), "l"(__cvta_generic_to_global(gsrc)) : "memory");
}
__device__ __forceinline__ void sts128z(uint32_t dst) {
    asm volatile("st.shared.v4.b32 [%0], {%1, %1, %1, %1};" :: "r"(dst), "r"(0u) : "memory");
}
#define CP_COMMIT() asm volatile("cp.async.commit_group;" ::: "memory")
#define CP_WAIT0()  asm volatile("cp.async.wait_group 0;" ::: "memory")

__device__ __forceinline__ void ldsm4(uint32_t* r, uint32_t addr) {
    asm volatile("ldmatrix.sync.aligned.m8n8.x4.shared.b16 {%0,%1,%2,%3}, [%4];"
                 : "=r"(r[0]), "=r"(r[1]), "=r"(r[2]), "=r"(r[3]) : "r"(addr));
}
__device__ __forceinline__ void mma16816(float* d, const uint32_t* a,
                                         uint32_t b0, uint32_t b1) {
    asm volatile("mma.sync.aligned.m16n8k16.row.col.f32.bf16.bf16.f32 "
                 "{%0,%1,%2,%3}, {%4,%5,%6,%7}, {%8,%9}, {%0,%1,%2,%3};"
                 : "+f"(d[0]), "+f"(d[1]), "+f"(d[2]), "+f"(d[3])
                 : "r"(a[0]), "r"(a[1]), "r"(a[2]), "r"(a[3]), "r"(b0), "r"(b1));
}

/* software exp2: deg-4 poly on t in [-0.5,0.5]; clamp handles underflow */
__device__ __forceinline__ float fexp2(float y) {
    y = fmaxf(y, -126.0f);
    float n = rintf(y);
    float t = y - n;
    float p = 0.00961801f;
    p = fmaf(p, t, 0.05550411f);
    p = fmaf(p, t, 0.24022651f);
    p = fmaf(p, t, 0.69314718f);
    p = fmaf(p, t, 1.0f);
    float sc = __int_as_float((int)fmaf(n, 8388608.0f, 1065353216.0f));
    return p * sc;
}

/* -------------------- kernel 0: F -> bf16 hi ------------------------------ */
__global__ __launch_bounds__(256)
void convF_kernel(const float* __restrict__ F) {
    size_t i = ((size_t)blockIdx.x * 256 + threadIdx.x) * 8;
    float4 x0 = *(const float4*)(F + i);
    float4 x1 = *(const float4*)(F + i + 4);
    float xs[8] = {x0.x, x0.y, x0.z, x0.w, x1.x, x1.y, x1.z, x1.w};
    __nv_bfloat16 hi[8];
#pragma unroll
    for (int j = 0; j < 8; ++j) hi[j] = __float2bfloat16(xs[j]);
    *(uint4*)((char*)g_Fhi + i * 2) = *(uint4*)hi;
}

/* ----------------- B tile prefetch: gmem -> smem (n-major, hi only) ------- */
__device__ __forceinline__ void prefetch_tile(uint32_t dstbase, int n0, int tid) {
#pragma unroll
    for (int i = 0; i < 8; ++i) {
        int seg = tid + (i << 8);            /* 0..2047 */
        int row = seg >> 5;                  /* 0..63 sample row */
        int ch  = seg & 31;                  /* 16B chunk within 512B row */
        uint32_t dst = dstbase + (uint32_t)row * BSTRIDE + (ch << 4);
        int gr = n0 + row;
        if (gr < NSAMP)
            cp16(dst, (const char*)g_Fhi + (((size_t)gr) << 9) + (ch << 4));
        else
            sts128z(dst);
    }
    CP_COMMIT();
}

/* --------------- kernel 1: mma.sync fused GEMM + online LSE --------------- */
__global__ void __launch_bounds__(256, 1)
fused_lse_mma(const float* __restrict__ A) {
    extern __shared__ __align__(16) char smem[];
    const uint32_t sb = smem_u32(smem);
    const int tid = threadIdx.x;
    const int lane = tid & 31;
    const int wid = tid >> 5;
    const int chunk = blockIdx.x;
    const int m0 = blockIdx.y * MTILE;

    /* ---- A fragments (hi/lo) resident in registers: m16 x k256 per warp --- */
    uint32_t Ah[16][4], Al[16][4];
    {
        const int r0 = m0 + wid * 16 + (lane >> 2);
        const float* A0 = A + (size_t)r0 * NFEAT;
        const float* A1 = A0 + 8 * NFEAT;
        const int kq = (lane & 3) * 2;
#pragma unroll
        for (int kc = 0; kc < 16; ++kc) {
#pragma unroll
            for (int q = 0; q < 4; ++q) {
                const float* src = ((q & 1) ? A1 : A0) + kc * 16 + ((q >> 1) << 3) + kq;
                float2 v = *(const float2*)src;
                __nv_bfloat16 h0 = __float2bfloat16(v.x);
                __nv_bfloat16 h1 = __float2bfloat16(v.y);
                __nv_bfloat16 l0 = __float2bfloat16(v.x - __bfloat162float(h0));
                __nv_bfloat16 l1 = __float2bfloat16(v.y - __bfloat162float(h1));
                Ah[kc][q] = ((uint32_t)__bfloat16_as_ushort(h1) << 16) | __bfloat16_as_ushort(h0);
                Al[kc][q] = ((uint32_t)__bfloat16_as_ushort(l1) << 16) | __bfloat16_as_ushort(l0);
            }
        }
    }

    const int t0 = (chunk * NTN) / NCHUNK;
    const int t1 = ((chunk + 1) * NTN) / NCHUNK;

    float mr0 = -INFINITY, sr0 = 0.f;   /* rows lane/4 and lane/4+8 of warp block */
    float mr1 = -INFINITY, sr1 = 0.f;

    /* ldmatrix lane addressing (constant per thread) */
    const uint32_t mat = lane >> 3;
    const uint32_t nrow = (lane & 7) + ((mat >> 1) << 3);
    const uint32_t kadd = (mat & 1) << 4;

    prefetch_tile(sb, t0 * NTILE, tid);

    for (int t = t0; t < t1; ++t) {
        const uint32_t buf = sb + (uint32_t)((t - t0) & 1) * BBYTES;
        CP_WAIT0();
        __syncthreads();
        if (t + 1 < t1)
            prefetch_tile(sb + (uint32_t)((t - t0 + 1) & 1) * BBYTES,
                          (t + 1) * NTILE, tid);

        float acc[8][4];
#pragma unroll
        for (int nf = 0; nf < 8; ++nf)
#pragma unroll
            for (int c = 0; c < 4; ++c) acc[nf][c] = 0.f;

#pragma unroll
        for (int kc = 0; kc < 16; ++kc) {
#pragma unroll
            for (int nfp = 0; nfp < 4; ++nfp) {
                uint32_t ah = buf + (nfp * 16 + nrow) * BSTRIDE + kc * 32 + kadd;
                uint32_t bh[4];
                ldsm4(bh, ah);
                mma16816(acc[nfp * 2],     Ah[kc], bh[0], bh[1]);
                mma16816(acc[nfp * 2],     Al[kc], bh[0], bh[1]);
                mma16816(acc[nfp * 2 + 1], Ah[kc], bh[2], bh[3]);
                mma16816(acc[nfp * 2 + 1], Al[kc], bh[2], bh[3]);
            }
        }

        /* ------ epilogue: per-row online (m, s); quad-shfls, no guards ----- */
        float mx0 = -INFINITY, mx1 = -INFINITY;
#pragma unroll
        for (int nf = 0; nf < 8; ++nf) {
            mx0 = fmaxf(mx0, fmaxf(acc[nf][0], acc[nf][1]));
            mx1 = fmaxf(mx1, fmaxf(acc[nf][2], acc[nf][3]));
        }
        mx0 = fmaxf(mx0, __shfl_xor_sync(0xffffffffu, mx0, 1));
        mx0 = fmaxf(mx0, __shfl_xor_sync(0xffffffffu, mx0, 2));
        mx1 = fmaxf(mx1, __shfl_xor_sync(0xffffffffu, mx1, 1));
        mx1 = fmaxf(mx1, __shfl_xor_sync(0xffffffffu, mx1, 2));

        /* tile contributes < 64*2^-30 of S for every row in this warp -> skip */
        bool sk = (mx0 < mr0 - SKIP_TH) && (mx1 < mr1 - SKIP_TH);
        if (__all_sync(0xffffffffu, sk)) continue;

        const float nm0 = fmaxf(mr0, mx0);
        const float nm1 = fmaxf(mr1, mx1);
        float e0 = 0.f, e1 = 0.f;
#pragma unroll
        for (int nf = 0; nf < 8; ++nf) {
            e0 += fexp2((acc[nf][0] - nm0) * KL2E) + fexp2((acc[nf][1] - nm0) * KL2E);
            e1 += fexp2((acc[nf][2] - nm1) * KL2E) + fexp2((acc[nf][3] - nm1) * KL2E);
        }
        e0 += __shfl_xor_sync(0xffffffffu, e0, 1);
        e0 += __shfl_xor_sync(0xffffffffu, e0, 2);
        e1 += __shfl_xor_sync(0xffffffffu, e1, 1);
        e1 += __shfl_xor_sync(0xffffffffu, e1, 2);

        sr0 = sr0 * fexp2((mr0 - nm0) * KL2E) + e0;  mr0 = nm0;
        sr1 = sr1 * fexp2((mr1 - nm1) * KL2E) + e1;  mr1 = nm1;
    }

    if ((lane & 3) == 0) {
        const int rbase = m0 + wid * 16 + (lane >> 2);
        g_partM[chunk * BATCHN + rbase]     = mr0 * INV_TEMP;
        g_partS[chunk * BATCHN + rbase]     = sr0;
        g_partM[chunk * BATCHN + rbase + 8] = mr1 * INV_TEMP;
        g_partS[chunk * BATCHN + rbase + 8] = sr1;
    }
}

/* ------------- kernel 2: merge chunk partials + target dot -> NLL --------- */
__global__ __launch_bounds__(256)
void merge_nll_kernel(const float* __restrict__ A, const float* __restrict__ F,
                      const int* __restrict__ T) {
    const int gw = (blockIdx.x * blockDim.x + threadIdx.x) >> 5;
    const int lane = threadIdx.x & 31;
    if (gw >= BATCHN) return;

    float M = -INFINITY, S = 0.f;
    if (lane < NCHUNK) {
        M = g_partM[lane * BATCHN + gw];
        S = g_partS[lane * BATCHN + gw];
    }
#pragma unroll
    for (int off = 16; off > 0; off >>= 1) {
        float oM = __shfl_down_sync(0xffffffffu, M, off);
        float oS = __shfl_down_sync(0xffffffffu, S, off);
        float nm = fmaxf(M, oM);
        if (nm == -INFINITY) { S = 0.f; }
        else { S = S * __expf(M - nm) + oS * __expf(oM - nm); }
        M = nm;
    }

    int tg = T[gw];
    tg = (tg < 0) ? 0 : ((tg >= NSAMP) ? NSAMP - 1 : tg);
    const float* ar = A + (size_t)gw * NFEAT;
    const float* fr = F + (size_t)tg * NFEAT;
    float td = 0.f;
#pragma unroll
    for (int k = lane; k < NFEAT; k += 32) td += ar[k] * fr[k];
#pragma unroll
    for (int off = 16; off > 0; off >>= 1) td += __shfl_down_sync(0xffffffffu, td, off);

    if (lane == 0) g_nll[gw] = M + logf(S) - td * INV_TEMP;
}

/* ---------------------------- kernel 3: mean ------------------------------ */
__global__ __launch_bounds__(256)
void mean_kernel(float* __restrict__ out) {
    __shared__ float sm[8];
    const int tid = threadIdx.x;
    const int lane = tid & 31, w = tid >> 5;
    float v = 0.f;
#pragma unroll
    for (int i = 0; i < 4; ++i) v += g_nll[tid + i * 256];
#pragma unroll
    for (int off = 16; off > 0; off >>= 1) v += __shfl_down_sync(0xffffffffu, v, off);
    if (lane == 0) sm[w] = v;
    __syncthreads();
    if (w == 0) {
        float x = (lane < 8) ? sm[lane] : 0.f;
#pragma unroll
        for (int off = 4; off > 0; off >>= 1) x += __shfl_down_sync(0xffffffffu, x, off);
        if (lane == 0) out[0] = x / (float)BATCHN;
    }
}

extern "C" void kernel_launch(void* const* d_in, const int* in_sizes, int n_in,
                              void* d_out, int out_size) {
    const float* A = nullptr;   /* inputs   [1024, 256]  f32 */
    const float* F = nullptr;   /* features [100000,256] f32 */
    const int*   T = nullptr;   /* targets  [1024]       i32 */
    for (int i = 0; i < n_in; ++i) {
        if (in_sizes[i] == BATCHN * NFEAT)      A = (const float*)d_in[i];
        else if (in_sizes[i] == NSAMP * NFEAT)  F = (const float*)d_in[i];
        else if (in_sizes[i] == BATCHN)         T = (const int*)d_in[i];
    }
    cudaFuncSetAttribute(fused_lse_mma,
                         cudaFuncAttributeMaxDynamicSharedMemorySize, SM_TOTAL);
    convF_kernel<<<(NSAMP * NFEAT) / (256 * 8), 256>>>(F);
    fused_lse_mma<<<dim3(NCHUNK, BATCHN / MTILE), 256, SM_TOTAL>>>(A);
    merge_nll_kernel<<<BATCHN / 8, 256>>>(A, F, T);
    mean_kernel<<<1, 256>>>((float*)d_out);
    (void)out_size;
}

// round 10
// speedup vs baseline: 8.0424x; 1.3560x over previous
#include <cuda_runtime.h>
#include <cuda_bf16.h>
#include <math.h>
#include <stdint.h>

#define BATCHN 1024
#define NFEAT 256
#define NSAMP 100000
#define INV_TEMP 20.0f
#define KL2E 28.85390081777927f      /* 20 * log2(e) */
#define SKIP_TH 1.05f                /* dot-units; 1.05*KL2E > 30 -> 2^-30 */

#define MTILE 128
#define NTILE 64
#define NCHUNK 18
#define NTN ((NSAMP + NTILE - 1) / NTILE)   /* 1563 */

#define BSTRIDE 528                   /* 512B row + 16B pad: conflict-free ldmatrix */
#define BBYTES (NTILE * BSTRIDE)      /* 33792 */
#define SM_TOTAL (2 * BBYTES)         /* double buffered hi-only = 67584 */

/* ------------------------- device scratch (no allocs) --------------------- */
__device__ __nv_bfloat16 g_Fhi[(size_t)NSAMP * NFEAT];
__device__ float g_partM[NCHUNK * BATCHN];
__device__ float g_partS[NCHUNK * BATCHN];
__device__ float g_nll[BATCHN];

/* ------------------------------ helpers ---------------------------------- */
__device__ __forceinline__ uint32_t smem_u32(const void* p) {
    uint32_t a;
    asm("{ .reg .u64 t; cvta.to.shared.u64 t, %1; cvt.u32.u64 %0, t; }"
        : "=r"(a) : "l"(p));
    return a;
}
__device__ __forceinline__ void cp16(uint32_t dst, const void* gsrc) {
    asm volatile("cp.async.cg.shared.global [%0], [%1], 16;"
                 :: "r"(dst), "l"(__cvta_generic_to_global(gsrc)) : "memory");
}
__device__ __forceinline__ void sts128z(uint32_t dst) {
    asm volatile("st.shared.v4.b32 [%0], {%1, %1, %1, %1};" :: "r"(dst), "r"(0u) : "memory");
}
#define CP_COMMIT() asm volatile("cp.async.commit_group;" ::: "memory")
#define CP_WAIT0()  asm volatile("cp.async.wait_group 0;" ::: "memory")

__device__ __forceinline__ void ldsm4(uint32_t* r, uint32_t addr) {
    asm volatile("ldmatrix.sync.aligned.m8n8.x4.shared.b16 {%0,%1,%2,%3}, [%4];"
                 : "=r"(r[0]), "=r"(r[1]), "=r"(r[2]), "=r"(r[3]) : "r"(addr));
}
__device__ __forceinline__ void mma16816(float* d, const uint32_t* a,
                                         uint32_t b0, uint32_t b1) {
    asm volatile("mma.sync.aligned.m16n8k16.row.col.f32.bf16.bf16.f32 "
                 "{%0,%1,%2,%3}, {%4,%5,%6,%7}, {%8,%9}, {%0,%1,%2,%3};"
                 : "+f"(d[0]), "+f"(d[1]), "+f"(d[2]), "+f"(d[3])
                 : "r"(a[0]), "r"(a[1]), "r"(a[2]), "r"(a[3]), "r"(b0), "r"(b1));
}

/* software exp2: deg-4 poly on t in [-0.5,0.5]; clamp handles underflow */
__device__ __forceinline__ float fexp2(float y) {
    y = fmaxf(y, -126.0f);
    float n = rintf(y);
    float t = y - n;
    float p = 0.00961801f;
    p = fmaf(p, t, 0.05550411f);
    p = fmaf(p, t, 0.24022651f);
    p = fmaf(p, t, 0.69314718f);
    p = fmaf(p, t, 1.0f);
    float sc = __int_as_float((int)fmaf(n, 8388608.0f, 1065353216.0f));
    return p * sc;
}

/* -------------------- kernel 0: F -> bf16 hi ------------------------------ */
__global__ __launch_bounds__(256)
void convF_kernel(const float* __restrict__ F) {
    size_t i = ((size_t)blockIdx.x * 256 + threadIdx.x) * 8;
    float4 x0 = *(const float4*)(F + i);
    float4 x1 = *(const float4*)(F + i + 4);
    float xs[8] = {x0.x, x0.y, x0.z, x0.w, x1.x, x1.y, x1.z, x1.w};
    __nv_bfloat16 hi[8];
#pragma unroll
    for (int j = 0; j < 8; ++j) hi[j] = __float2bfloat16(xs[j]);
    *(uint4*)((char*)g_Fhi + i * 2) = *(uint4*)hi;
}

/* ----------------- B tile prefetch: gmem -> smem (n-major, hi only) ------- */
__device__ __forceinline__ void prefetch_tile(uint32_t dstbase, int n0, int tid) {
#pragma unroll
    for (int i = 0; i < 8; ++i) {
        int seg = tid + (i << 8);            /* 0..2047 */
        int row = seg >> 5;                  /* 0..63 sample row */
        int ch  = seg & 31;                  /* 16B chunk within 512B row */
        uint32_t dst = dstbase + (uint32_t)row * BSTRIDE + (ch << 4);
        int gr = n0 + row;
        if (gr < NSAMP)
            cp16(dst, (const char*)g_Fhi + (((size_t)gr) << 9) + (ch << 4));
        else
            sts128z(dst);
    }
    CP_COMMIT();
}

/* --------------- kernel 1: mma.sync fused GEMM + online LSE --------------- */
__global__ void __launch_bounds__(256, 1)
fused_lse_mma(const float* __restrict__ A) {
    extern __shared__ __align__(16) char smem[];
    const uint32_t sb = smem_u32(smem);
    const int tid = threadIdx.x;
    const int lane = tid & 31;
    const int wid = tid >> 5;
    const int chunk = blockIdx.x;
    const int m0 = blockIdx.y * MTILE;

    /* ---- A fragments (bf16 hi) resident in registers: m16 x k256 / warp --- */
    uint32_t Ah[16][4];
    {
        const int r0 = m0 + wid * 16 + (lane >> 2);
        const float* A0 = A + (size_t)r0 * NFEAT;
        const float* A1 = A0 + 8 * NFEAT;
        const int kq = (lane & 3) * 2;
#pragma unroll
        for (int kc = 0; kc < 16; ++kc) {
#pragma unroll
            for (int q = 0; q < 4; ++q) {
                const float* src = ((q & 1) ? A1 : A0) + kc * 16 + ((q >> 1) << 3) + kq;
                float2 v = *(const float2*)src;
                __nv_bfloat16 h0 = __float2bfloat16(v.x);
                __nv_bfloat16 h1 = __float2bfloat16(v.y);
                Ah[kc][q] = ((uint32_t)__bfloat16_as_ushort(h1) << 16) | __bfloat16_as_ushort(h0);
            }
        }
    }

    const int t0 = (chunk * NTN) / NCHUNK;
    const int t1 = ((chunk + 1) * NTN) / NCHUNK;

    float mr0 = -INFINITY, sr0 = 0.f;   /* rows lane/4 and lane/4+8 of warp block */
    float mr1 = -INFINITY, sr1 = 0.f;

    /* ldmatrix lane addressing (constant per thread) */
    const uint32_t mat = lane >> 3;
    const uint32_t nrow = (lane & 7) + ((mat >> 1) << 3);
    const uint32_t kadd = (mat & 1) << 4;

    prefetch_tile(sb, t0 * NTILE, tid);

    for (int t = t0; t < t1; ++t) {
        const uint32_t buf = sb + (uint32_t)((t - t0) & 1) * BBYTES;
        CP_WAIT0();
        __syncthreads();
        if (t + 1 < t1)
            prefetch_tile(sb + (uint32_t)((t - t0 + 1) & 1) * BBYTES,
                          (t + 1) * NTILE, tid);

        float acc[8][4];
#pragma unroll
        for (int nf = 0; nf < 8; ++nf)
#pragma unroll
            for (int c = 0; c < 4; ++c) acc[nf][c] = 0.f;

#pragma unroll
        for (int kc = 0; kc < 16; ++kc) {
#pragma unroll
            for (int nfp = 0; nfp < 4; ++nfp) {
                uint32_t ah = buf + (nfp * 16 + nrow) * BSTRIDE + kc * 32 + kadd;
                uint32_t bh[4];
                ldsm4(bh, ah);
                mma16816(acc[nfp * 2],     Ah[kc], bh[0], bh[1]);
                mma16816(acc[nfp * 2 + 1], Ah[kc], bh[2], bh[3]);
            }
        }

        /* ------ epilogue: per-row online (m, s); quad-shfls, no guards ----- */
        float mx0 = -INFINITY, mx1 = -INFINITY;
#pragma unroll
        for (int nf = 0; nf < 8; ++nf) {
            mx0 = fmaxf(mx0, fmaxf(acc[nf][0], acc[nf][1]));
            mx1 = fmaxf(mx1, fmaxf(acc[nf][2], acc[nf][3]));
        }
        mx0 = fmaxf(mx0, __shfl_xor_sync(0xffffffffu, mx0, 1));
        mx0 = fmaxf(mx0, __shfl_xor_sync(0xffffffffu, mx0, 2));
        mx1 = fmaxf(mx1, __shfl_xor_sync(0xffffffffu, mx1, 1));
        mx1 = fmaxf(mx1, __shfl_xor_sync(0xffffffffu, mx1, 2));

        /* tile contributes < 64*2^-30 of S for every row in this warp -> skip */
        bool sk = (mx0 < mr0 - SKIP_TH) && (mx1 < mr1 - SKIP_TH);
        if (__all_sync(0xffffffffu, sk)) continue;

        const float nm0 = fmaxf(mr0, mx0);
        const float nm1 = fmaxf(mr1, mx1);
        float e0 = 0.f, e1 = 0.f;
#pragma unroll
        for (int nf = 0; nf < 8; ++nf) {
            e0 += fexp2((acc[nf][0] - nm0) * KL2E) + fexp2((acc[nf][1] - nm0) * KL2E);
            e1 += fexp2((acc[nf][2] - nm1) * KL2E) + fexp2((acc[nf][3] - nm1) * KL2E);
        }
        e0 += __shfl_xor_sync(0xffffffffu, e0, 1);
        e0 += __shfl_xor_sync(0xffffffffu, e0, 2);
        e1 += __shfl_xor_sync(0xffffffffu, e1, 1);
        e1 += __shfl_xor_sync(0xffffffffu, e1, 2);

        sr0 = sr0 * fexp2((mr0 - nm0) * KL2E) + e0;  mr0 = nm0;
        sr1 = sr1 * fexp2((mr1 - nm1) * KL2E) + e1;  mr1 = nm1;
    }

    if ((lane & 3) == 0) {
        const int rbase = m0 + wid * 16 + (lane >> 2);
        g_partM[chunk * BATCHN + rbase]     = mr0 * INV_TEMP;
        g_partS[chunk * BATCHN + rbase]     = sr0;
        g_partM[chunk * BATCHN + rbase + 8] = mr1 * INV_TEMP;
        g_partS[chunk * BATCHN + rbase + 8] = sr1;
    }
}

/* ------------- kernel 2: merge chunk partials + target dot -> NLL --------- */
__global__ __launch_bounds__(256)
void merge_nll_kernel(const float* __restrict__ A, const float* __restrict__ F,
                      const int* __restrict__ T) {
    const int gw = (blockIdx.x * blockDim.x + threadIdx.x) >> 5;
    const int lane = threadIdx.x & 31;
    if (gw >= BATCHN) return;

    float M = -INFINITY, S = 0.f;
    if (lane < NCHUNK) {
        M = g_partM[lane * BATCHN + gw];
        S = g_partS[lane * BATCHN + gw];
    }
#pragma unroll
    for (int off = 16; off > 0; off >>= 1) {
        float oM = __shfl_down_sync(0xffffffffu, M, off);
        float oS = __shfl_down_sync(0xffffffffu, S, off);
        float nm = fmaxf(M, oM);
        if (nm == -INFINITY) { S = 0.f; }
        else { S = S * __expf(M - nm) + oS * __expf(oM - nm); }
        M = nm;
    }

    int tg = T[gw];
    tg = (tg < 0) ? 0 : ((tg >= NSAMP) ? NSAMP - 1 : tg);
    const float* ar = A + (size_t)gw * NFEAT;
    const float* fr = F + (size_t)tg * NFEAT;
    float td = 0.f;
#pragma unroll
    for (int k = lane; k < NFEAT; k += 32) td += ar[k] * fr[k];
#pragma unroll
    for (int off = 16; off > 0; off >>= 1) td += __shfl_down_sync(0xffffffffu, td, off);

    if (lane == 0) g_nll[gw] = M + logf(S) - td * INV_TEMP;
}

/* ---------------------------- kernel 3: mean ------------------------------ */
__global__ __launch_bounds__(256)
void mean_kernel(float* __restrict__ out) {
    __shared__ float sm[8];
    const int tid = threadIdx.x;
    const int lane = tid & 31, w = tid >> 5;
    float v = 0.f;
#pragma unroll
    for (int i = 0; i < 4; ++i) v += g_nll[tid + i * 256];
#pragma unroll
    for (int off = 16; off > 0; off >>= 1) v += __shfl_down_sync(0xffffffffu, v, off);
    if (lane == 0) sm[w] = v;
    __syncthreads();
    if (w == 0) {
        float x = (lane < 8) ? sm[lane] : 0.f;
#pragma unroll
        for (int off = 4; off > 0; off >>= 1) x += __shfl_down_sync(0xffffffffu, x, off);
        if (lane == 0) out[0] = x / (float)BATCHN;
    }
}

extern "C" void kernel_launch(void* const* d_in, const int* in_sizes, int n_in,
                              void* d_out, int out_size) {
    const float* A = nullptr;   /* inputs   [1024, 256]  f32 */
    const float* F = nullptr;   /* features [100000,256] f32 */
    const int*   T = nullptr;   /* targets  [1024]       i32 */
    for (int i = 0; i < n_in; ++i) {
        if (in_sizes[i] == BATCHN * NFEAT)      A = (const float*)d_in[i];
        else if (in_sizes[i] == NSAMP * NFEAT)  F = (const float*)d_in[i];
        else if (in_sizes[i] == BATCHN)         T = (const int*)d_in[i];
    }
    cudaFuncSetAttribute(fused_lse_mma,
                         cudaFuncAttributeMaxDynamicSharedMemorySize, SM_TOTAL);
    convF_kernel<<<(NSAMP * NFEAT) / (256 * 8), 256>>>(F);
    fused_lse_mma<<<dim3(NCHUNK, BATCHN / MTILE), 256, SM_TOTAL>>>(A);
    merge_nll_kernel<<<BATCHN / 8, 256>>>(A, F, T);
    mean_kernel<<<1, 256>>>((float*)d_out);
    (void)out_size;
}